// round 1
// baseline (speedup 1.0000x reference)
#include <cuda_runtime.h>
#include <cstdint>

#define MM 8192
#define KK 4096
#define NN 4096

// Scratch (device globals — no allocation in kernel_launch allowed)
__device__ signed char g_qA[(size_t)MM * KK];   // [M][K] row-major int8
__device__ signed char g_qBT[(size_t)NN * KK];  // [N][K] K-contiguous int8 (B transposed)
__device__ float g_lsc[MM];
__device__ float g_rsc[NN];
__device__ float g_pmax[32 * NN];

// ---------------------------------------------------------------------------
// Kernel 1: per-row absmax + quantize of lhs. One block per row (4096 floats).
// ---------------------------------------------------------------------------
__global__ __launch_bounds__(256) void quant_lhs_kernel(const float* __restrict__ lhs) {
    int row = blockIdx.x;
    int t = threadIdx.x;
    const float4* src = (const float4*)(lhs + (size_t)row * KK);
    float4 v[4];
    float m = 0.0f;
#pragma unroll
    for (int i = 0; i < 4; i++) {
        v[i] = src[i * 256 + t];
        m = fmaxf(m, fmaxf(fmaxf(fabsf(v[i].x), fabsf(v[i].y)),
                           fmaxf(fabsf(v[i].z), fabsf(v[i].w))));
    }
#pragma unroll
    for (int o = 16; o > 0; o >>= 1) m = fmaxf(m, __shfl_xor_sync(0xffffffffu, m, o));
    __shared__ float red[8];
    if ((t & 31) == 0) red[t >> 5] = m;
    __syncthreads();
    m = red[0];
#pragma unroll
    for (int i = 1; i < 8; i++) m = fmaxf(m, red[i]);

    float scale = m / 127.0f;           // true division (matches jnp exactly)
    if (scale == 0.0f) scale = 1.0f;
    if (t == 0) g_lsc[row] = scale;

    int* qdst = (int*)(g_qA + (size_t)row * KK);
#pragma unroll
    for (int i = 0; i < 4; i++) {
        float r0 = fminf(fmaxf(rintf(v[i].x / scale), -127.0f), 127.0f);
        float r1 = fminf(fmaxf(rintf(v[i].y / scale), -127.0f), 127.0f);
        float r2 = fminf(fmaxf(rintf(v[i].z / scale), -127.0f), 127.0f);
        float r3 = fminf(fmaxf(rintf(v[i].w / scale), -127.0f), 127.0f);
        int packed = (((int)r0) & 255) | ((((int)r1) & 255) << 8) |
                     ((((int)r2) & 255) << 16) | ((((int)r3) & 255) << 24);
        qdst[i * 256 + t] = packed;
    }
}

// ---------------------------------------------------------------------------
// Kernel 2a/2b: per-column absmax of rhs (two-stage for parallelism)
// ---------------------------------------------------------------------------
__global__ __launch_bounds__(256) void rhs_pmax_kernel(const float* __restrict__ rhs) {
    int n = blockIdx.x * 256 + threadIdx.x;
    int k0 = blockIdx.y * 128;
    const float* p = rhs + (size_t)k0 * NN + n;
    float m = 0.0f;
#pragma unroll 8
    for (int k = 0; k < 128; k++) m = fmaxf(m, fabsf(p[(size_t)k * NN]));
    g_pmax[blockIdx.y * NN + n] = m;
}

__global__ __launch_bounds__(256) void rhs_scale_kernel() {
    int n = blockIdx.x * 256 + threadIdx.x;
    float m = 0.0f;
#pragma unroll
    for (int i = 0; i < 32; i++) m = fmaxf(m, g_pmax[i * NN + n]);
    float s = m / 127.0f;
    if (s == 0.0f) s = 1.0f;
    g_rsc[n] = s;
}

// ---------------------------------------------------------------------------
// Kernel 3: quantize rhs and transpose into [N][K] int8 (64x64 smem tiles)
// ---------------------------------------------------------------------------
__global__ __launch_bounds__(256) void quant_rhs_kernel(const float* __restrict__ rhs) {
    __shared__ signed char tile[64][68];
    int k0 = blockIdx.y * 64, n0 = blockIdx.x * 64;
    int t = threadIdx.x;
    int nl = t & 63;
    int kl0 = t >> 6;  // 0..3
    float s = g_rsc[n0 + nl];
#pragma unroll
    for (int i = 0; i < 16; i++) {
        int kl = kl0 + i * 4;
        float v = rhs[(size_t)(k0 + kl) * NN + n0 + nl];
        float r = fminf(fmaxf(rintf(v / s), -127.0f), 127.0f);
        tile[kl][nl] = (signed char)(int)r;
    }
    __syncthreads();
    int k4 = t & 15;   // 0..15 -> k bytes k4*4
    int nl2 = t >> 4;  // 0..15
#pragma unroll
    for (int i = 0; i < 4; i++) {
        int nn = nl2 + i * 16;
        char4 c;
        c.x = tile[k4 * 4 + 0][nn];
        c.y = tile[k4 * 4 + 1][nn];
        c.z = tile[k4 * 4 + 2][nn];
        c.w = tile[k4 * 4 + 3][nn];
        *(char4*)&g_qBT[(size_t)(n0 + nn) * KK + k0 + k4 * 4] = c;
    }
}

// ---------------------------------------------------------------------------
// Kernel 4: int8 GEMM via mma.sync.m16n8k32 + fused dequant epilogue
// Block tile 128x128x64, 8 warps (2m x 4n), warp tile 64x32.
// Smem row stride 80B => conflict-free fragment LDS.
// ---------------------------------------------------------------------------
__device__ __forceinline__ void mma_s8(int& c0, int& c1, int& c2, int& c3,
                                       int a0, int a1, int a2, int a3,
                                       int b0, int b1) {
    asm volatile(
        "mma.sync.aligned.m16n8k32.row.col.s32.s8.s8.s32 "
        "{%0,%1,%2,%3}, {%4,%5,%6,%7}, {%8,%9}, {%0,%1,%2,%3};\n"
        : "+r"(c0), "+r"(c1), "+r"(c2), "+r"(c3)
        : "r"(a0), "r"(a1), "r"(a2), "r"(a3), "r"(b0), "r"(b1));
}

__global__ __launch_bounds__(256) void gemm_s8_kernel(float* __restrict__ out) {
    __shared__ signed char As[128 * 80];
    __shared__ signed char Bs[128 * 80];

    int tid = threadIdx.x;
    int warp = tid >> 5, lane = tid & 31;
    int wm = (warp >> 2) * 64;  // warp m offset in block tile
    int wn = (warp & 3) * 32;   // warp n offset
    int bm = blockIdx.y * 128, bn = blockIdx.x * 128;
    int grp = lane >> 2, tq = lane & 3;

    int acc[4][4][4];
#pragma unroll
    for (int mi = 0; mi < 4; mi++)
#pragma unroll
        for (int ni = 0; ni < 4; ni++)
#pragma unroll
            for (int r = 0; r < 4; r++) acc[mi][ni][r] = 0;

    for (int kt = 0; kt < KK / 64; kt++) {
#pragma unroll
        for (int p = 0; p < 2; p++) {
            int idx = p * 256 + tid;
            int r = idx >> 2, s = idx & 3;
            *(int4*)(As + r * 80 + s * 16) =
                *(const int4*)(g_qA + (size_t)(bm + r) * KK + kt * 64 + s * 16);
            *(int4*)(Bs + r * 80 + s * 16) =
                *(const int4*)(g_qBT + (size_t)(bn + r) * KK + kt * 64 + s * 16);
        }
        __syncthreads();

#pragma unroll
        for (int kk = 0; kk < 2; kk++) {
            int a[4][4], b[4][2];
#pragma unroll
            for (int mi = 0; mi < 4; mi++) {
                const signed char* base = As + (wm + mi * 16 + grp) * 80 + kk * 32 + tq * 4;
                a[mi][0] = *(const int*)(base);
                a[mi][1] = *(const int*)(base + 8 * 80);
                a[mi][2] = *(const int*)(base + 16);
                a[mi][3] = *(const int*)(base + 8 * 80 + 16);
            }
#pragma unroll
            for (int ni = 0; ni < 4; ni++) {
                const signed char* base = Bs + (wn + ni * 8 + grp) * 80 + kk * 32 + tq * 4;
                b[ni][0] = *(const int*)(base);
                b[ni][1] = *(const int*)(base + 16);
            }
#pragma unroll
            for (int mi = 0; mi < 4; mi++)
#pragma unroll
                for (int ni = 0; ni < 4; ni++)
                    mma_s8(acc[mi][ni][0], acc[mi][ni][1], acc[mi][ni][2], acc[mi][ni][3],
                           a[mi][0], a[mi][1], a[mi][2], a[mi][3], b[ni][0], b[ni][1]);
        }
        __syncthreads();
    }

    // Epilogue: dequant by lhs_scale[m] * rhs_scale[n]
#pragma unroll
    for (int mi = 0; mi < 4; mi++) {
        int gm0 = bm + wm + mi * 16 + grp;
        float s0 = g_lsc[gm0];
        float s1 = g_lsc[gm0 + 8];
#pragma unroll
        for (int ni = 0; ni < 4; ni++) {
            int gn = bn + wn + ni * 8 + tq * 2;
            float r0 = g_rsc[gn];
            float r1 = g_rsc[gn + 1];
            float2 o0, o1;
            o0.x = (float)acc[mi][ni][0] * s0 * r0;
            o0.y = (float)acc[mi][ni][1] * s0 * r1;
            o1.x = (float)acc[mi][ni][2] * s1 * r0;
            o1.y = (float)acc[mi][ni][3] * s1 * r1;
            *(float2*)(out + (size_t)gm0 * NN + gn) = o0;
            *(float2*)(out + (size_t)(gm0 + 8) * NN + gn) = o1;
        }
    }
}

// ---------------------------------------------------------------------------
extern "C" void kernel_launch(void* const* d_in, const int* in_sizes, int n_in,
                              void* d_out, int out_size) {
    const float* lhs = (const float*)d_in[0];
    const float* rhs = (const float*)d_in[1];
    if (n_in >= 2 && in_sizes[0] == KK * NN && in_sizes[1] == MM * KK) {
        // defensive: swap if metadata order differs
        const float* t = lhs; lhs = rhs; rhs = t;
    }
    float* out = (float*)d_out;

    quant_lhs_kernel<<<MM, 256>>>(lhs);
    rhs_pmax_kernel<<<dim3(NN / 256, 32), 256>>>(rhs);
    rhs_scale_kernel<<<NN / 256, 256>>>();
    quant_rhs_kernel<<<dim3(NN / 64, KK / 64), 256>>>(rhs);
    gemm_s8_kernel<<<dim3(NN / 128, MM / 128), 256>>>(out);
}

// round 3
// speedup vs baseline: 1.0041x; 1.0041x over previous
#include <cuda_runtime.h>
#include <cstdint>

#define MM 8192
#define KK 4096
#define NN 4096

// GEMM tiling
#define BM 128
#define BN 256
#define BKB 64            // K bytes per stage
#define NSTAGE 4
#define NCHUNK (KK / BKB) // 64
#define ROWSTRIDE 80      // smem row stride (conflict-free for fragment LDS)

// Scratch (device globals — no allocation allowed)
__device__ signed char g_qA[(size_t)MM * KK];   // [M][K] int8, K contiguous
__device__ signed char g_qBT[(size_t)NN * KK];  // [N][K] int8, K contiguous
__device__ float g_lsc[MM];
__device__ float g_rsc[NN];
__device__ float g_pmax[32 * NN];

// ---------------------------------------------------------------------------
// Kernel 1: per-row absmax + quantize of lhs
// ---------------------------------------------------------------------------
__global__ __launch_bounds__(256) void quant_lhs_kernel(const float* __restrict__ lhs) {
    int row = blockIdx.x;
    int t = threadIdx.x;
    const float4* src = (const float4*)(lhs + (size_t)row * KK);
    float4 v[4];
    float m = 0.0f;
#pragma unroll
    for (int i = 0; i < 4; i++) {
        v[i] = src[i * 256 + t];
        m = fmaxf(m, fmaxf(fmaxf(fabsf(v[i].x), fabsf(v[i].y)),
                           fmaxf(fabsf(v[i].z), fabsf(v[i].w))));
    }
#pragma unroll
    for (int o = 16; o > 0; o >>= 1) m = fmaxf(m, __shfl_xor_sync(0xffffffffu, m, o));
    __shared__ float red[8];
    if ((t & 31) == 0) red[t >> 5] = m;
    __syncthreads();
    m = red[0];
#pragma unroll
    for (int i = 1; i < 8; i++) m = fmaxf(m, red[i]);

    float scale = m / 127.0f;
    if (scale == 0.0f) scale = 1.0f;
    if (t == 0) g_lsc[row] = scale;

    int* qdst = (int*)(g_qA + (size_t)row * KK);
#pragma unroll
    for (int i = 0; i < 4; i++) {
        float r0 = fminf(fmaxf(rintf(v[i].x / scale), -127.0f), 127.0f);
        float r1 = fminf(fmaxf(rintf(v[i].y / scale), -127.0f), 127.0f);
        float r2 = fminf(fmaxf(rintf(v[i].z / scale), -127.0f), 127.0f);
        float r3 = fminf(fmaxf(rintf(v[i].w / scale), -127.0f), 127.0f);
        int packed = (((int)r0) & 255) | ((((int)r1) & 255) << 8) |
                     ((((int)r2) & 255) << 16) | ((((int)r3) & 255) << 24);
        qdst[i * 256 + t] = packed;
    }
}

// ---------------------------------------------------------------------------
// Kernel 2a/2b: per-column absmax of rhs
// ---------------------------------------------------------------------------
__global__ __launch_bounds__(256) void rhs_pmax_kernel(const float* __restrict__ rhs) {
    int n = blockIdx.x * 256 + threadIdx.x;
    int k0 = blockIdx.y * 128;
    const float* p = rhs + (size_t)k0 * NN + n;
    float m = 0.0f;
#pragma unroll 8
    for (int k = 0; k < 128; k++) m = fmaxf(m, fabsf(p[(size_t)k * NN]));
    g_pmax[blockIdx.y * NN + n] = m;
}

__global__ __launch_bounds__(256) void rhs_scale_kernel() {
    int n = blockIdx.x * 256 + threadIdx.x;
    float m = 0.0f;
#pragma unroll
    for (int i = 0; i < 32; i++) m = fmaxf(m, g_pmax[i * NN + n]);
    float s = m / 127.0f;
    if (s == 0.0f) s = 1.0f;
    g_rsc[n] = s;
}

// ---------------------------------------------------------------------------
// Kernel 3: quantize rhs + transpose into [N][K]
// ---------------------------------------------------------------------------
__global__ __launch_bounds__(256) void quant_rhs_kernel(const float* __restrict__ rhs) {
    __shared__ signed char tile[64][68];
    int k0 = blockIdx.y * 64, n0 = blockIdx.x * 64;
    int t = threadIdx.x;
    int nl = t & 63;
    int kl0 = t >> 6;
    float s = g_rsc[n0 + nl];
#pragma unroll
    for (int i = 0; i < 16; i++) {
        int kl = kl0 + i * 4;
        float v = rhs[(size_t)(k0 + kl) * NN + n0 + nl];
        float r = fminf(fmaxf(rintf(v / s), -127.0f), 127.0f);
        tile[kl][nl] = (signed char)(int)r;
    }
    __syncthreads();
    int k4 = t & 15;
    int nl2 = t >> 4;
#pragma unroll
    for (int i = 0; i < 4; i++) {
        int nn = nl2 + i * 16;
        char4 c;
        c.x = tile[k4 * 4 + 0][nn];
        c.y = tile[k4 * 4 + 1][nn];
        c.z = tile[k4 * 4 + 2][nn];
        c.w = tile[k4 * 4 + 3][nn];
        *(char4*)&g_qBT[(size_t)(n0 + nn) * KK + k0 + k4 * 4] = c;
    }
}

// ---------------------------------------------------------------------------
// Kernel 4: pipelined int8 GEMM (mma.sync m16n8k32) + fused dequant
// Block 128x256, 8 warps (2m x 4n), warp tile 64x64, 4-stage cp.async.
// ---------------------------------------------------------------------------
__device__ __forceinline__ void mma_s8(int& c0, int& c1, int& c2, int& c3,
                                       int a0, int a1, int a2, int a3,
                                       int b0, int b1) {
    asm volatile(
        "mma.sync.aligned.m16n8k32.row.col.s32.s8.s8.s32 "
        "{%0,%1,%2,%3}, {%4,%5,%6,%7}, {%8,%9}, {%0,%1,%2,%3};\n"
        : "+r"(c0), "+r"(c1), "+r"(c2), "+r"(c3)
        : "r"(a0), "r"(a1), "r"(a2), "r"(a3), "r"(b0), "r"(b1));
}

__device__ __forceinline__ void cp16(uint32_t smem, const void* g) {
    asm volatile("cp.async.cg.shared.global [%0], [%1], 16;" :: "r"(smem), "l"(g));
}

#define A_STAGE (BM * ROWSTRIDE)             // 10240
#define B_STAGE (BN * ROWSTRIDE)             // 20480
#define STAGE (A_STAGE + B_STAGE)            // 30720
#define SMEM_REQ (NSTAGE * STAGE)            // 122880

__global__ void __launch_bounds__(256, 1)
gemm_s8_kernel(float* __restrict__ out) {
    extern __shared__ signed char sm[];
    uint32_t smb = (uint32_t)__cvta_generic_to_shared(sm);

    int tid = threadIdx.x;
    int warp = tid >> 5, lane = tid & 31;
    int wm = (warp >> 2) * 64;   // 0 or 64
    int wn = (warp & 3) * 64;    // 0..192
    int bm = blockIdx.y * BM, bn = blockIdx.x * BN;
    int grp = lane >> 2, tq = lane & 3;

    // cp.async source pointers / smem offsets (each thread: 2 A chunks, 4 B chunks)
    const signed char* gA[2];
    uint32_t sA[2];
#pragma unroll
    for (int p = 0; p < 2; p++) {
        int i = p * 256 + tid;
        int r = i >> 2, s = i & 3;
        gA[p] = g_qA + (size_t)(bm + r) * KK + s * 16;
        sA[p] = smb + r * ROWSTRIDE + s * 16;
    }
    const signed char* gB[4];
    uint32_t sB[4];
#pragma unroll
    for (int p = 0; p < 4; p++) {
        int i = p * 256 + tid;
        int r = i >> 2, s = i & 3;
        gB[p] = g_qBT + (size_t)(bn + r) * KK + s * 16;
        sB[p] = smb + A_STAGE + r * ROWSTRIDE + s * 16;
    }

    int acc[4][8][4];
#pragma unroll
    for (int mi = 0; mi < 4; mi++)
#pragma unroll
        for (int ni = 0; ni < 8; ni++)
#pragma unroll
            for (int r = 0; r < 4; r++) acc[mi][ni][r] = 0;

    // Prologue: stages 0..2
#pragma unroll
    for (int st = 0; st < NSTAGE - 1; st++) {
#pragma unroll
        for (int p = 0; p < 2; p++) cp16(sA[p] + st * STAGE, gA[p] + st * BKB);
#pragma unroll
        for (int p = 0; p < 4; p++) cp16(sB[p] + st * STAGE, gB[p] + st * BKB);
        asm volatile("cp.async.commit_group;");
    }

    uint32_t aBase = smb + (wm + grp) * ROWSTRIDE + tq * 4;
    uint32_t bBase = smb + A_STAGE + (wn + grp) * ROWSTRIDE + tq * 4;

    for (int kt = 0; kt < NCHUNK; kt++) {
        asm volatile("cp.async.wait_group 2;");
        __syncthreads();

        // Issue next-stage loads (overlap with compute below)
        if (kt + NSTAGE - 1 < NCHUNK) {
            int st = (kt + NSTAGE - 1) & (NSTAGE - 1);
            int ko = (kt + NSTAGE - 1) * BKB;
#pragma unroll
            for (int p = 0; p < 2; p++) cp16(sA[p] + st * STAGE, gA[p] + ko);
#pragma unroll
            for (int p = 0; p < 4; p++) cp16(sB[p] + st * STAGE, gB[p] + ko);
            asm volatile("cp.async.commit_group;");
        }

        uint32_t stoff = (kt & (NSTAGE - 1)) * STAGE;
#pragma unroll
        for (int kk = 0; kk < 2; kk++) {  // two K=32 steps per 64B chunk
            int a[4][4], b[8][2];
#pragma unroll
            for (int mi = 0; mi < 4; mi++) {
                uint32_t p = aBase + stoff + mi * 16 * ROWSTRIDE + kk * 32;
                asm volatile("ld.shared.b32 %0, [%1];" : "=r"(a[mi][0]) : "r"(p));
                asm volatile("ld.shared.b32 %0, [%1];" : "=r"(a[mi][1]) : "r"(p + 8 * ROWSTRIDE));
                asm volatile("ld.shared.b32 %0, [%1];" : "=r"(a[mi][2]) : "r"(p + 16));
                asm volatile("ld.shared.b32 %0, [%1];" : "=r"(a[mi][3]) : "r"(p + 8 * ROWSTRIDE + 16));
            }
#pragma unroll
            for (int ni = 0; ni < 8; ni++) {
                uint32_t p = bBase + stoff + ni * 8 * ROWSTRIDE + kk * 32;
                asm volatile("ld.shared.b32 %0, [%1];" : "=r"(b[ni][0]) : "r"(p));
                asm volatile("ld.shared.b32 %0, [%1];" : "=r"(b[ni][1]) : "r"(p + 16));
            }
#pragma unroll
            for (int mi = 0; mi < 4; mi++)
#pragma unroll
                for (int ni = 0; ni < 8; ni++)
                    mma_s8(acc[mi][ni][0], acc[mi][ni][1], acc[mi][ni][2], acc[mi][ni][3],
                           a[mi][0], a[mi][1], a[mi][2], a[mi][3], b[ni][0], b[ni][1]);
        }
        __syncthreads();
    }

    // Epilogue: dequant + store
#pragma unroll
    for (int mi = 0; mi < 4; mi++) {
        int gm0 = bm + wm + mi * 16 + grp;
        float s0 = g_lsc[gm0];
        float s1 = g_lsc[gm0 + 8];
#pragma unroll
        for (int ni = 0; ni < 8; ni++) {
            int gn = bn + wn + ni * 8 + tq * 2;
            float r0 = g_rsc[gn];
            float r1 = g_rsc[gn + 1];
            float2 o0, o1;
            o0.x = (float)acc[mi][ni][0] * s0 * r0;
            o0.y = (float)acc[mi][ni][1] * s0 * r1;
            o1.x = (float)acc[mi][ni][2] * s1 * r0;
            o1.y = (float)acc[mi][ni][3] * s1 * r1;
            *(float2*)(out + (size_t)gm0 * NN + gn) = o0;
            *(float2*)(out + (size_t)(gm0 + 8) * NN + gn) = o1;
        }
    }
}

// ---------------------------------------------------------------------------
extern "C" void kernel_launch(void* const* d_in, const int* in_sizes, int n_in,
                              void* d_out, int out_size) {
    const float* lhs = (const float*)d_in[0];
    const float* rhs = (const float*)d_in[1];
    if (n_in >= 2 && in_sizes[0] == KK * NN && in_sizes[1] == MM * KK) {
        const float* t = lhs; lhs = rhs; rhs = t;
    }
    float* out = (float*)d_out;

    cudaFuncSetAttribute(gemm_s8_kernel, cudaFuncAttributeMaxDynamicSharedMemorySize, SMEM_REQ);

    quant_lhs_kernel<<<MM, 256>>>(lhs);
    rhs_pmax_kernel<<<dim3(NN / 256, 32), 256>>>(rhs);
    rhs_scale_kernel<<<NN / 256, 256>>>();
    quant_rhs_kernel<<<dim3(NN / 64, KK / 64), 256>>>(rhs);
    gemm_s8_kernel<<<dim3(NN / BN, MM / BM), 256, SMEM_REQ>>>(out);
}

// round 4
// speedup vs baseline: 2.3292x; 2.3197x over previous
#include <cuda_runtime.h>
#include <cuda_fp16.h>
#include <cstdint>

#define MM 8192
#define KK 4096
#define NN 4096

// GEMM tiling (fp16 mainloop)
#define BM 256
#define BN 128
#define BK 64             // K elems per stage (128 bytes of fp16)
#define NST 3
#define NCHUNK (KK / BK)  // 64
#define RS 144            // smem row stride bytes (128B data + 16B pad)

#define A_STG (BM * RS)           // 36864
#define B_STG (BN * RS)           // 18432
#define STG (A_STG + B_STG)       // 55296
#define SMEM_REQ (NST * STG)      // 165888

// Scratch (device globals — no allocation allowed)
__device__ __half g_qA[(size_t)MM * KK];   // [M][K] fp16 (integer values)
__device__ __half g_qBT[(size_t)NN * KK];  // [N][K] fp16 (B transposed)
__device__ float g_lsc[MM];
__device__ float g_rsc[NN];
__device__ float g_pmax[32 * NN];

// ---------------------------------------------------------------------------
// Kernel 1: per-row absmax + quantize of lhs -> fp16 integers
// ---------------------------------------------------------------------------
__global__ __launch_bounds__(256) void quant_lhs_kernel(const float* __restrict__ lhs) {
    int row = blockIdx.x;
    int t = threadIdx.x;
    const float4* src = (const float4*)(lhs + (size_t)row * KK);
    float4 v[4];
    float m = 0.0f;
#pragma unroll
    for (int i = 0; i < 4; i++) {
        v[i] = src[i * 256 + t];
        m = fmaxf(m, fmaxf(fmaxf(fabsf(v[i].x), fabsf(v[i].y)),
                           fmaxf(fabsf(v[i].z), fabsf(v[i].w))));
    }
#pragma unroll
    for (int o = 16; o > 0; o >>= 1) m = fmaxf(m, __shfl_xor_sync(0xffffffffu, m, o));
    __shared__ float red[8];
    if ((t & 31) == 0) red[t >> 5] = m;
    __syncthreads();
    m = red[0];
#pragma unroll
    for (int i = 1; i < 8; i++) m = fmaxf(m, red[i]);

    float scale = m / 127.0f;
    if (scale == 0.0f) scale = 1.0f;
    if (t == 0) g_lsc[row] = scale;

    __half2* qdst = (__half2*)(g_qA + (size_t)row * KK);
#pragma unroll
    for (int i = 0; i < 4; i++) {
        float r0 = fminf(fmaxf(rintf(v[i].x / scale), -127.0f), 127.0f);
        float r1 = fminf(fmaxf(rintf(v[i].y / scale), -127.0f), 127.0f);
        float r2 = fminf(fmaxf(rintf(v[i].z / scale), -127.0f), 127.0f);
        float r3 = fminf(fmaxf(rintf(v[i].w / scale), -127.0f), 127.0f);
        qdst[(i * 256 + t) * 2 + 0] = __floats2half2_rn(r0, r1);
        qdst[(i * 256 + t) * 2 + 1] = __floats2half2_rn(r2, r3);
    }
}

// ---------------------------------------------------------------------------
// Kernel 2a/2b: per-column absmax of rhs
// ---------------------------------------------------------------------------
__global__ __launch_bounds__(256) void rhs_pmax_kernel(const float* __restrict__ rhs) {
    int n = blockIdx.x * 256 + threadIdx.x;
    int k0 = blockIdx.y * 128;
    const float* p = rhs + (size_t)k0 * NN + n;
    float m = 0.0f;
#pragma unroll 8
    for (int k = 0; k < 128; k++) m = fmaxf(m, fabsf(p[(size_t)k * NN]));
    g_pmax[blockIdx.y * NN + n] = m;
}

__global__ __launch_bounds__(256) void rhs_scale_kernel() {
    int n = blockIdx.x * 256 + threadIdx.x;
    float m = 0.0f;
#pragma unroll
    for (int i = 0; i < 32; i++) m = fmaxf(m, g_pmax[i * NN + n]);
    float s = m / 127.0f;
    if (s == 0.0f) s = 1.0f;
    g_rsc[n] = s;
}

// ---------------------------------------------------------------------------
// Kernel 3: quantize rhs + transpose into [N][K] fp16
// ---------------------------------------------------------------------------
__global__ __launch_bounds__(256) void quant_rhs_kernel(const float* __restrict__ rhs) {
    __shared__ __half tile[64][68];
    int k0 = blockIdx.y * 64, n0 = blockIdx.x * 64;
    int t = threadIdx.x;
    int nl = t & 63;
    int kl0 = t >> 6;
    float s = g_rsc[n0 + nl];
#pragma unroll
    for (int i = 0; i < 16; i++) {
        int kl = kl0 + i * 4;
        float v = rhs[(size_t)(k0 + kl) * NN + n0 + nl];
        float r = fminf(fmaxf(rintf(v / s), -127.0f), 127.0f);
        tile[kl][nl] = __float2half_rn(r);
    }
    __syncthreads();
    int k4 = t & 15;
    int nl2 = t >> 4;
#pragma unroll
    for (int i = 0; i < 4; i++) {
        int nn = nl2 + i * 16;
        __half h0 = tile[k4 * 4 + 0][nn];
        __half h1 = tile[k4 * 4 + 1][nn];
        __half h2 = tile[k4 * 4 + 2][nn];
        __half h3 = tile[k4 * 4 + 3][nn];
        __half2 p0 = __halves2half2(h0, h1);
        __half2 p1 = __halves2half2(h2, h3);
        uint2 pk;
        pk.x = *(uint32_t*)&p0;
        pk.y = *(uint32_t*)&p1;
        *(uint2*)&g_qBT[(size_t)(n0 + nn) * KK + k0 + k4 * 4] = pk;
    }
}

// ---------------------------------------------------------------------------
// Kernel 4: pipelined fp16 GEMM (mma.sync m16n8k16 f32 accum) + fused dequant
// Block 256x128, 16 warps (4m x 4n), warp tile 64x32, 3-stage cp.async.
// ---------------------------------------------------------------------------
__device__ __forceinline__ void mma_f16(float& c0, float& c1, float& c2, float& c3,
                                        uint32_t a0, uint32_t a1, uint32_t a2, uint32_t a3,
                                        uint32_t b0, uint32_t b1) {
    asm volatile(
        "mma.sync.aligned.m16n8k16.row.col.f32.f16.f16.f32 "
        "{%0,%1,%2,%3}, {%4,%5,%6,%7}, {%8,%9}, {%0,%1,%2,%3};\n"
        : "+f"(c0), "+f"(c1), "+f"(c2), "+f"(c3)
        : "r"(a0), "r"(a1), "r"(a2), "r"(a3), "r"(b0), "r"(b1));
}

__device__ __forceinline__ void cp16(uint32_t smem, const void* g) {
    asm volatile("cp.async.cg.shared.global [%0], [%1], 16;" :: "r"(smem), "l"(g));
}

__global__ void __launch_bounds__(512, 1)
gemm_f16_kernel(float* __restrict__ out) {
    extern __shared__ signed char sm[];
    uint32_t smb = (uint32_t)__cvta_generic_to_shared(sm);

    int tid = threadIdx.x;
    int warp = tid >> 5, lane = tid & 31;
    int wm = (warp & 3) * 64;    // warp m offset
    int wn = (warp >> 2) * 32;   // warp n offset
    int bm = blockIdx.y * BM, bn = blockIdx.x * BN;
    int grp = lane >> 2, tq = lane & 3;

    // cp.async mapping: A 4 chunks/thread, B 2 chunks/thread (16B each)
    const __half* gA[4];
    uint32_t sA[4];
#pragma unroll
    for (int p = 0; p < 4; p++) {
        int i = p * 512 + tid;
        int r = i >> 3, s = i & 7;
        gA[p] = g_qA + (size_t)(bm + r) * KK + s * 8;
        sA[p] = smb + r * RS + s * 16;
    }
    const __half* gB[2];
    uint32_t sB[2];
#pragma unroll
    for (int p = 0; p < 2; p++) {
        int i = p * 512 + tid;
        int r = i >> 3, s = i & 7;
        gB[p] = g_qBT + (size_t)(bn + r) * KK + s * 8;
        sB[p] = smb + A_STG + r * RS + s * 16;
    }

    float acc[4][4][4];
#pragma unroll
    for (int mi = 0; mi < 4; mi++)
#pragma unroll
        for (int ni = 0; ni < 4; ni++)
#pragma unroll
            for (int r = 0; r < 4; r++) acc[mi][ni][r] = 0.0f;

    // Prologue: stages 0..1
#pragma unroll
    for (int st = 0; st < NST - 1; st++) {
#pragma unroll
        for (int p = 0; p < 4; p++) cp16(sA[p] + st * STG, gA[p] + st * BK);
#pragma unroll
        for (int p = 0; p < 2; p++) cp16(sB[p] + st * STG, gB[p] + st * BK);
        asm volatile("cp.async.commit_group;");
    }

    uint32_t aBase = smb + (wm + grp) * RS + tq * 4;
    uint32_t bBase = smb + A_STG + (wn + grp) * RS + tq * 4;

    int stage = 0;
    for (int kt = 0; kt < NCHUNK; kt++) {
        asm volatile("cp.async.wait_group 1;");
        __syncthreads();

        if (kt + NST - 1 < NCHUNK) {
            int st = stage + (NST - 1) >= NST ? stage + (NST - 1) - NST : stage + (NST - 1);
            int ko = (kt + NST - 1) * BK;
#pragma unroll
            for (int p = 0; p < 4; p++) cp16(sA[p] + st * STG, gA[p] + ko);
#pragma unroll
            for (int p = 0; p < 2; p++) cp16(sB[p] + st * STG, gB[p] + ko);
        }
        asm volatile("cp.async.commit_group;");

        uint32_t stoff = stage * STG;
#pragma unroll
        for (int ks = 0; ks < 4; ks++) {   // four K=16 steps per 64-elem chunk
            uint32_t a[4][4], b[4][2];
#pragma unroll
            for (int mi = 0; mi < 4; mi++) {
                uint32_t p = aBase + stoff + mi * 16 * RS + ks * 32;
                asm volatile("ld.shared.b32 %0, [%1];" : "=r"(a[mi][0]) : "r"(p));
                asm volatile("ld.shared.b32 %0, [%1];" : "=r"(a[mi][1]) : "r"(p + 8 * RS));
                asm volatile("ld.shared.b32 %0, [%1];" : "=r"(a[mi][2]) : "r"(p + 16));
                asm volatile("ld.shared.b32 %0, [%1];" : "=r"(a[mi][3]) : "r"(p + 8 * RS + 16));
            }
#pragma unroll
            for (int ni = 0; ni < 4; ni++) {
                uint32_t p = bBase + stoff + ni * 8 * RS + ks * 32;
                asm volatile("ld.shared.b32 %0, [%1];" : "=r"(b[ni][0]) : "r"(p));
                asm volatile("ld.shared.b32 %0, [%1];" : "=r"(b[ni][1]) : "r"(p + 16));
            }
#pragma unroll
            for (int mi = 0; mi < 4; mi++)
#pragma unroll
                for (int ni = 0; ni < 4; ni++)
                    mma_f16(acc[mi][ni][0], acc[mi][ni][1], acc[mi][ni][2], acc[mi][ni][3],
                            a[mi][0], a[mi][1], a[mi][2], a[mi][3], b[ni][0], b[ni][1]);
        }
        stage = (stage + 1 == NST) ? 0 : stage + 1;
        __syncthreads();
    }

    // Epilogue: dequant + store
#pragma unroll
    for (int mi = 0; mi < 4; mi++) {
        int gm0 = bm + wm + mi * 16 + grp;
        float s0 = g_lsc[gm0];
        float s1 = g_lsc[gm0 + 8];
#pragma unroll
        for (int ni = 0; ni < 4; ni++) {
            int gn = bn + wn + ni * 8 + tq * 2;
            float r0 = g_rsc[gn];
            float r1 = g_rsc[gn + 1];
            float2 o0, o1;
            o0.x = acc[mi][ni][0] * s0 * r0;
            o0.y = acc[mi][ni][1] * s0 * r1;
            o1.x = acc[mi][ni][2] * s1 * r0;
            o1.y = acc[mi][ni][3] * s1 * r1;
            *(float2*)(out + (size_t)gm0 * NN + gn) = o0;
            *(float2*)(out + (size_t)(gm0 + 8) * NN + gn) = o1;
        }
    }
}

// ---------------------------------------------------------------------------
extern "C" void kernel_launch(void* const* d_in, const int* in_sizes, int n_in,
                              void* d_out, int out_size) {
    const float* lhs = (const float*)d_in[0];
    const float* rhs = (const float*)d_in[1];
    if (n_in >= 2 && in_sizes[0] == KK * NN && in_sizes[1] == MM * KK) {
        const float* t = lhs; lhs = rhs; rhs = t;
    }
    float* out = (float*)d_out;

    cudaFuncSetAttribute(gemm_f16_kernel, cudaFuncAttributeMaxDynamicSharedMemorySize, SMEM_REQ);

    quant_lhs_kernel<<<MM, 256>>>(lhs);
    rhs_pmax_kernel<<<dim3(NN / 256, 32), 256>>>(rhs);
    rhs_scale_kernel<<<NN / 256, 256>>>();
    quant_rhs_kernel<<<dim3(NN / 64, KK / 64), 256>>>(rhs);
    gemm_f16_kernel<<<dim3(NN / BN, MM / BM), 512, SMEM_REQ>>>(out);
}

// round 5
// speedup vs baseline: 2.6519x; 1.1385x over previous
#include <cuda_runtime.h>
#include <cuda_fp16.h>
#include <cstdint>

#define MM 8192
#define KK 4096
#define NN 4096

// GEMM tiling (fp16 mainloop)
#define BM 256
#define BN 128
#define BK 64             // K elems per stage (128 bytes of fp16)
#define NST 4
#define NCHUNK (KK / BK)  // 64
#define RS 144            // smem row stride bytes (128B data + 16B pad)

#define A_STG (BM * RS)           // 36864
#define B_STG (BN * RS)           // 18432
#define STG (A_STG + B_STG)       // 55296
#define SMEM_REQ (NST * STG)      // 221184

// Scratch (device globals — no allocation allowed)
__device__ __half g_qA[(size_t)MM * KK];   // [M][K] fp16 (integer values)
__device__ __half g_qBT[(size_t)NN * KK];  // [N][K] fp16 (B transposed)
__device__ float g_lsc[MM];
__device__ float g_rsc[NN];
__device__ float g_pmax[32 * NN];

// ---------------------------------------------------------------------------
// Kernel 1: per-row absmax + quantize of lhs -> fp16 integers
// ---------------------------------------------------------------------------
__global__ __launch_bounds__(256) void quant_lhs_kernel(const float* __restrict__ lhs) {
    int row = blockIdx.x;
    int t = threadIdx.x;
    const float4* src = (const float4*)(lhs + (size_t)row * KK);
    float4 v[4];
    float m = 0.0f;
#pragma unroll
    for (int i = 0; i < 4; i++) {
        v[i] = src[i * 256 + t];
        m = fmaxf(m, fmaxf(fmaxf(fabsf(v[i].x), fabsf(v[i].y)),
                           fmaxf(fabsf(v[i].z), fabsf(v[i].w))));
    }
#pragma unroll
    for (int o = 16; o > 0; o >>= 1) m = fmaxf(m, __shfl_xor_sync(0xffffffffu, m, o));
    __shared__ float red[8];
    if ((t & 31) == 0) red[t >> 5] = m;
    __syncthreads();
    m = red[0];
#pragma unroll
    for (int i = 1; i < 8; i++) m = fmaxf(m, red[i]);

    float scale = m / 127.0f;
    if (scale == 0.0f) scale = 1.0f;
    if (t == 0) g_lsc[row] = scale;

    __half2* qdst = (__half2*)(g_qA + (size_t)row * KK);
#pragma unroll
    for (int i = 0; i < 4; i++) {
        float r0 = fminf(fmaxf(rintf(v[i].x / scale), -127.0f), 127.0f);
        float r1 = fminf(fmaxf(rintf(v[i].y / scale), -127.0f), 127.0f);
        float r2 = fminf(fmaxf(rintf(v[i].z / scale), -127.0f), 127.0f);
        float r3 = fminf(fmaxf(rintf(v[i].w / scale), -127.0f), 127.0f);
        qdst[(i * 256 + t) * 2 + 0] = __floats2half2_rn(r0, r1);
        qdst[(i * 256 + t) * 2 + 1] = __floats2half2_rn(r2, r3);
    }
}

// ---------------------------------------------------------------------------
// Kernel 2a/2b: per-column absmax of rhs
// ---------------------------------------------------------------------------
__global__ __launch_bounds__(256) void rhs_pmax_kernel(const float* __restrict__ rhs) {
    int n = blockIdx.x * 256 + threadIdx.x;
    int k0 = blockIdx.y * 128;
    const float* p = rhs + (size_t)k0 * NN + n;
    float m = 0.0f;
#pragma unroll 8
    for (int k = 0; k < 128; k++) m = fmaxf(m, fabsf(p[(size_t)k * NN]));
    g_pmax[blockIdx.y * NN + n] = m;
}

__global__ __launch_bounds__(256) void rhs_scale_kernel() {
    int n = blockIdx.x * 256 + threadIdx.x;
    float m = 0.0f;
#pragma unroll
    for (int i = 0; i < 32; i++) m = fmaxf(m, g_pmax[i * NN + n]);
    float s = m / 127.0f;
    if (s == 0.0f) s = 1.0f;
    g_rsc[n] = s;
}

// ---------------------------------------------------------------------------
// Kernel 3: quantize rhs + transpose into [N][K] fp16
// ---------------------------------------------------------------------------
__global__ __launch_bounds__(256) void quant_rhs_kernel(const float* __restrict__ rhs) {
    __shared__ __half tile[64][68];
    int k0 = blockIdx.y * 64, n0 = blockIdx.x * 64;
    int t = threadIdx.x;
    int nl = t & 63;
    int kl0 = t >> 6;
    float s = g_rsc[n0 + nl];
#pragma unroll
    for (int i = 0; i < 16; i++) {
        int kl = kl0 + i * 4;
        float v = rhs[(size_t)(k0 + kl) * NN + n0 + nl];
        float r = fminf(fmaxf(rintf(v / s), -127.0f), 127.0f);
        tile[kl][nl] = __float2half_rn(r);
    }
    __syncthreads();
    int k4 = t & 15;
    int nl2 = t >> 4;
#pragma unroll
    for (int i = 0; i < 4; i++) {
        int nn = nl2 + i * 16;
        __half2 p0 = __halves2half2(tile[k4 * 4 + 0][nn], tile[k4 * 4 + 1][nn]);
        __half2 p1 = __halves2half2(tile[k4 * 4 + 2][nn], tile[k4 * 4 + 3][nn]);
        uint2 pk;
        pk.x = *(uint32_t*)&p0;
        pk.y = *(uint32_t*)&p1;
        *(uint2*)&g_qBT[(size_t)(n0 + nn) * KK + k0 + k4 * 4] = pk;
    }
}

// ---------------------------------------------------------------------------
// Kernel 4: pipelined fp16 GEMM with ldmatrix fragment loads
// Block 256x128, 16 warps (4m x 4n), warp tile 64x32, 4-stage cp.async.
// ---------------------------------------------------------------------------
__device__ __forceinline__ void mma_f16(float& c0, float& c1, float& c2, float& c3,
                                        uint32_t a0, uint32_t a1, uint32_t a2, uint32_t a3,
                                        uint32_t b0, uint32_t b1) {
    asm volatile(
        "mma.sync.aligned.m16n8k16.row.col.f32.f16.f16.f32 "
        "{%0,%1,%2,%3}, {%4,%5,%6,%7}, {%8,%9}, {%0,%1,%2,%3};\n"
        : "+f"(c0), "+f"(c1), "+f"(c2), "+f"(c3)
        : "r"(a0), "r"(a1), "r"(a2), "r"(a3), "r"(b0), "r"(b1));
}

__device__ __forceinline__ void ldsm4(uint32_t& r0, uint32_t& r1, uint32_t& r2, uint32_t& r3,
                                      uint32_t addr) {
    asm volatile("ldmatrix.sync.aligned.m8n8.x4.shared.b16 {%0,%1,%2,%3}, [%4];"
                 : "=r"(r0), "=r"(r1), "=r"(r2), "=r"(r3) : "r"(addr));
}

__device__ __forceinline__ void cp16(uint32_t smem, const void* g) {
    asm volatile("cp.async.cg.shared.global [%0], [%1], 16;" :: "r"(smem), "l"(g));
}

__global__ void __launch_bounds__(512, 1)
gemm_f16_kernel(float* __restrict__ out) {
    extern __shared__ signed char sm[];
    uint32_t smb = (uint32_t)__cvta_generic_to_shared(sm);

    int tid = threadIdx.x;
    int warp = tid >> 5, lane = tid & 31;
    int wm = (warp & 3) * 64;    // warp m offset
    int wn = (warp >> 2) * 32;   // warp n offset
    int bm = blockIdx.y * BM, bn = blockIdx.x * BN;
    int grp = lane >> 2, tq = lane & 3;

    // cp.async mapping: A 4 chunks/thread, B 2 chunks/thread (16B each)
    const __half* gA[4];
    uint32_t sA[4];
#pragma unroll
    for (int p = 0; p < 4; p++) {
        int i = p * 512 + tid;
        int r = i >> 3, s = i & 7;
        gA[p] = g_qA + (size_t)(bm + r) * KK + s * 8;
        sA[p] = smb + r * RS + s * 16;
    }
    const __half* gB[2];
    uint32_t sB[2];
#pragma unroll
    for (int p = 0; p < 2; p++) {
        int i = p * 512 + tid;
        int r = i >> 3, s = i & 7;
        gB[p] = g_qBT + (size_t)(bn + r) * KK + s * 8;
        sB[p] = smb + A_STG + r * RS + s * 16;
    }

    // ldmatrix per-lane base addresses
    // A x4: m0 rows 0-7 k+0 | m1 rows 8-15 k+0 | m2 rows 0-7 k+16B | m3 rows 8-15 k+16B
    uint32_t aLd = smb + (wm + (lane & 15)) * RS + (lane >> 4) * 16;
    // B x4: m0 n+0-7 k+0 | m1 n+0-7 k+16B | m2 n+8-15 k+0 | m3 n+8-15 k+16B
    uint32_t bLd = smb + A_STG +
                   (wn + ((lane >> 4) & 1) * 8 + (lane & 7)) * RS + ((lane >> 3) & 1) * 16;

    float acc[4][4][4];
#pragma unroll
    for (int mi = 0; mi < 4; mi++)
#pragma unroll
        for (int ni = 0; ni < 4; ni++)
#pragma unroll
            for (int r = 0; r < 4; r++) acc[mi][ni][r] = 0.0f;

    // Prologue: stages 0..NST-2
#pragma unroll
    for (int st = 0; st < NST - 1; st++) {
#pragma unroll
        for (int p = 0; p < 4; p++) cp16(sA[p] + st * STG, gA[p] + st * BK);
#pragma unroll
        for (int p = 0; p < 2; p++) cp16(sB[p] + st * STG, gB[p] + st * BK);
        asm volatile("cp.async.commit_group;");
    }

    int stage = 0;
    for (int kt = 0; kt < NCHUNK; kt++) {
        asm volatile("cp.async.wait_group %0;" :: "n"(NST - 2));
        __syncthreads();

        if (kt + NST - 1 < NCHUNK) {
            int st = stage + (NST - 1) >= NST ? stage - 1 : stage + NST - 1;
            int ko = (kt + NST - 1) * BK;
#pragma unroll
            for (int p = 0; p < 4; p++) cp16(sA[p] + st * STG, gA[p] + ko);
#pragma unroll
            for (int p = 0; p < 2; p++) cp16(sB[p] + st * STG, gB[p] + ko);
        }
        asm volatile("cp.async.commit_group;");

        uint32_t stoff = stage * STG;
#pragma unroll
        for (int ks = 0; ks < 4; ks++) {   // four K=16 steps per 64-elem chunk
            uint32_t a[4][4], b[4][2];
#pragma unroll
            for (int mi = 0; mi < 4; mi++)
                ldsm4(a[mi][0], a[mi][1], a[mi][2], a[mi][3],
                      aLd + stoff + mi * 16 * RS + ks * 32);
#pragma unroll
            for (int np = 0; np < 2; np++)
                ldsm4(b[2 * np][0], b[2 * np][1], b[2 * np + 1][0], b[2 * np + 1][1],
                      bLd + stoff + np * 16 * RS + ks * 32);
#pragma unroll
            for (int mi = 0; mi < 4; mi++)
#pragma unroll
                for (int ni = 0; ni < 4; ni++)
                    mma_f16(acc[mi][ni][0], acc[mi][ni][1], acc[mi][ni][2], acc[mi][ni][3],
                            a[mi][0], a[mi][1], a[mi][2], a[mi][3], b[ni][0], b[ni][1]);
        }
        stage = (stage + 1 == NST) ? 0 : stage + 1;
    }

    // Epilogue: dequant + store
#pragma unroll
    for (int mi = 0; mi < 4; mi++) {
        int gm0 = bm + wm + mi * 16 + grp;
        float s0 = g_lsc[gm0];
        float s1 = g_lsc[gm0 + 8];
#pragma unroll
        for (int ni = 0; ni < 4; ni++) {
            int gn = bn + wn + ni * 8 + tq * 2;
            float r0 = g_rsc[gn];
            float r1 = g_rsc[gn + 1];
            float2 o0, o1;
            o0.x = acc[mi][ni][0] * s0 * r0;
            o0.y = acc[mi][ni][1] * s0 * r1;
            o1.x = acc[mi][ni][2] * s1 * r0;
            o1.y = acc[mi][ni][3] * s1 * r1;
            *(float2*)(out + (size_t)gm0 * NN + gn) = o0;
            *(float2*)(out + (size_t)(gm0 + 8) * NN + gn) = o1;
        }
    }
}

// ---------------------------------------------------------------------------
extern "C" void kernel_launch(void* const* d_in, const int* in_sizes, int n_in,
                              void* d_out, int out_size) {
    const float* lhs = (const float*)d_in[0];
    const float* rhs = (const float*)d_in[1];
    if (n_in >= 2 && in_sizes[0] == KK * NN && in_sizes[1] == MM * KK) {
        const float* t = lhs; lhs = rhs; rhs = t;
    }
    float* out = (float*)d_out;

    cudaFuncSetAttribute(gemm_f16_kernel, cudaFuncAttributeMaxDynamicSharedMemorySize, SMEM_REQ);

    quant_lhs_kernel<<<MM, 256>>>(lhs);
    rhs_pmax_kernel<<<dim3(NN / 256, 32), 256>>>(rhs);
    rhs_scale_kernel<<<NN / 256, 256>>>();
    quant_rhs_kernel<<<dim3(NN / 64, KK / 64), 256>>>(rhs);
    gemm_f16_kernel<<<dim3(NN / BN, MM / BM), 512, SMEM_REQ>>>(out);
}